// round 9
// baseline (speedup 1.0000x reference)
#include <cuda_runtime.h>
#include <cstdint>

// Problem constants
#define NB   8
#define TPD  2048
#define ED   4096
#define TD   16384
#define VD   17
#define OUTROWS 131072
#define KS   8             // K-splits
#define KCHUNK 512         // ED/KS
#define KT   16            // K per pipeline stage
#define NSTAGE (KCHUNK/KT) // 32
#define ENT  256           // entries per k3 block
#define RMAX 16384         // hard upper bound on per-batch masked count

typedef unsigned long long ull;

// Scratch (device globals)
__device__ float g_WeffQ[8 * 1024 * 32];      // [s0][q][32] quad-interleaved Weff
__device__ float g_beff[8];
__device__ unsigned short g_entry[NB * RMAX]; // per-batch sorted masked t values
__device__ int   g_count[NB];                 // per-batch masked count
__device__ float g_part[(size_t)KS * NB * RMAX * 8];  // [ks][n][r][s]

// ---------------------------------------------------------------------------
__device__ __forceinline__ void ffma2(ull& d, ull a, ull b) {
    asm("fma.rn.f32x2 %0, %1, %2, %0;" : "+l"(d) : "l"(a), "l"(b));
}
__device__ __forceinline__ void ldgsts16(void* dst, const void* src) {
    unsigned saddr = (unsigned)__cvta_generic_to_shared(dst);
    asm volatile("cp.async.cg.shared.global [%0], [%1], 16;\n" :: "r"(saddr), "l"(src));
}
__device__ __forceinline__ void cp_commit() {
    asm volatile("cp.async.commit_group;\n" ::: "memory");
}
template <int N>
__device__ __forceinline__ void cp_wait() {
    asm volatile("cp.async.wait_group %0;\n" :: "n"(N) : "memory");
}

// ---------------------------------------------------------------------------
// K01 fused, 1024 threads/block:
//   blocks [0,8): per-batch argmax + masked compaction (single rank scan)
//   blocks [8,264): WeffQ for 16 e-values each (+beff at block 8)
// ---------------------------------------------------------------------------
__global__ __launch_bounds__(1024) void k01(const float* __restrict__ W1,
                                            const float* __restrict__ W2,
                                            const float* __restrict__ b1,
                                            const float* __restrict__ b2,
                                            const int* __restrict__ value,
                                            const int* __restrict__ depth) {
    int bid = blockIdx.x;
    int tid = threadIdx.x;

    if (bid >= 8) {
        // ---- Weff: 16 e-values per block ----
        __shared__ __align__(16) float w2s[512];
        __shared__ __align__(16) float w1r[16][512];
        int e0 = (bid - 8) * 16;
        if (tid < 128) ((float4*)w2s)[tid] = ((const float4*)W2)[tid];
        ((float4*)&w1r[0][0])[tid]        = ((const float4*)(W1 + (size_t)e0 * 512))[tid];
        ((float4*)&w1r[0][0])[tid + 1024] = ((const float4*)(W1 + (size_t)e0 * 512))[tid + 1024];
        __syncthreads();
        int sub = tid >> 6;       // which e (0..15)
        int t64 = tid & 63;
        int s0 = t64 >> 3, s = t64 & 7;
        int e = e0 + sub;
        float acc = 0.f;
#pragma unroll
        for (int c = 0; c < 64; c++) acc += w1r[sub][c * 8 + s0] * w2s[c * 8 + s];
        int q = e >> 2, p = (e >> 1) & 1, h = e & 1;
        g_WeffQ[(s0 * 1024 + q) * 32 + p * 16 + s * 2 + h] = acc;
        if (bid == 8 && tid < 8) {
            float a = 0.f;
#pragma unroll
            for (int c = 0; c < 64; c++) a += b1[c] * w2s[c * 8 + tid];
            g_beff[tid] = a + b2[0];
        }
    } else {
        // ---- prep: batch n, coalesced int4, 4 passes, single rank scan ----
        int n = bid;
        const int* dep = depth + n * TD;
        const int* val = value + n * TD;
        __shared__ int s_idx;
        __shared__ int wsum[32];
        __shared__ int sb_r;
        __shared__ int pass_tot;

        int lane = tid & 31, wid = tid >> 5;  // 32 warps

        int maxv = dep[TD - 1];
        if (tid == 0) { s_idx = TD; sb_r = 0; }
        __syncthreads();
        // argmax: first index where dep hits max (dep sorted ascending)
        for (int t0 = tid * 4; t0 < TD; t0 += 4096) {
            int4 d = *(const int4*)(dep + t0);
            int prev = (t0 == 0) ? (maxv - 1) : dep[t0 - 1];
            if (d.x == maxv && prev < maxv) atomicMin(&s_idx, t0);
            if (d.y == maxv && d.x < maxv) atomicMin(&s_idx, t0 + 1);
            if (d.z == maxv && d.y < maxv) atomicMin(&s_idx, t0 + 2);
            if (d.w == maxv && d.z < maxv) atomicMin(&s_idx, t0 + 3);
        }
        __syncthreads();
        int idx = s_idx;

        for (int pass = 0; pass < 4; pass++) {
            int t0 = pass * 4096 + tid * 4;
            int4 vv = *(const int4*)(val + t0);
            int vj[4] = {vv.x, vv.y, vv.z, vv.w};
            unsigned mb = 0;
            int cnt = 0;
#pragma unroll
            for (int j = 0; j < 4; j++) {
                int t = t0 + j;
                bool m = (t < idx) && (vj[j] == 2);
                mb |= ((unsigned)m) << j;
                cnt += (int)m;
            }
            int v = cnt;
#pragma unroll
            for (int o = 1; o < 32; o <<= 1) {
                int u = __shfl_up_sync(0xffffffffu, v, o);
                if (lane >= o) v += u;
            }
            if (lane == 31) wsum[wid] = v;
            __syncthreads();
            if (wid == 0) {
                int w = wsum[lane];
                int wi = w;
#pragma unroll
                for (int o = 1; o < 32; o <<= 1) {
                    int u = __shfl_up_sync(0xffffffffu, wi, o);
                    if (lane >= o) wi += u;
                }
                wsum[lane] = wi - w;
                if (lane == 31) pass_tot = wi;
            }
            __syncthreads();
            int r = sb_r + wsum[wid] + (v - cnt);
#pragma unroll
            for (int j = 0; j < 4; j++) {
                if ((mb >> j) & 1u) {
                    g_entry[n * RMAX + r] = (unsigned short)(t0 + j);
                    r++;
                }
            }
            __syncthreads();
            if (tid == 0) sb_r += pass_tot;
            __syncthreads();
        }
        if (tid == 0) g_count[n] = sb_r;
    }
}

// ---------------------------------------------------------------------------
// K3: dedup GEMM. 256 threads/block, 256 entries/block (1 per thread).
// Entries are t-sorted -> same-tp adjacent; block-local scan builds unique-tp
// rows (~137). X staged ONCE per unique tp via cp.async (XSTRIDE=20,
// conflict-free); W holds all 8 s0 tiles (pad 132 -> per-lane s0 conflict-
// free); f32x2 FMA. K split by ks (512 floats), 32 double-buffered KT=16
// stages. Partials -> g_part[ks][n][r][s], r = global entry rank.
// blockIdx.x = rb*8 + ks, blockIdx.y = n.
// ---------------------------------------------------------------------------
#define XSTRIDE 20

__global__ __launch_bounds__(256) void k3_heavy(const float* __restrict__ x) {
    int bx = blockIdx.x;
    int ks = bx & 7, rb = bx >> 3;
    int n = blockIdx.y;
    int cnt = g_count[n];
    int e0 = rb * ENT;
    if (e0 >= cnt) return;
    int tid = threadIdx.x;

    __shared__ __align__(16) float Xs[2][ENT][XSTRIDE];   // 40KB
    __shared__ __align__(16) float Wsm[2][8 * 132];       // 8.25KB
    __shared__ int   tps[ENT];
    __shared__ unsigned char s0s[ENT];
    __shared__ short lrow_s[ENT];
    __shared__ short utp[ENT];
    __shared__ int wsc[8];
    __shared__ int s_nu;

    // ---- prologue: entries, unique-row scan ----
    {
        int gr = e0 + tid;
        int e = (gr < cnt) ? (int)g_entry[n * RMAX + gr] : 0xFFFF;
        tps[tid] = e >> 3;
        s0s[tid] = (unsigned char)(e & 7);
    }
    __syncthreads();
    {
        int lane = tid & 31, wid = tid >> 5;  // 8 warps
        int f = (tid == 0) ? 1 : (tps[tid] != tps[tid - 1]);
        int v = f;
#pragma unroll
        for (int o = 1; o < 32; o <<= 1) {
            int u = __shfl_up_sync(0xffffffffu, v, o);
            if (lane >= o) v += u;
        }
        if (lane == 31) wsc[wid] = v;
        __syncthreads();
        if (tid < 32) {
            int w = (tid < 8) ? wsc[tid] : 0;
            int wi = w;
#pragma unroll
            for (int o = 1; o < 8; o <<= 1) {
                int u = __shfl_up_sync(0xffffffffu, wi, o);
                if (lane >= o) wi += u;
            }
            if (tid < 8) wsc[tid] = wi - w;
            if (tid == 7) s_nu = wi;
        }
        __syncthreads();
        int lr = wsc[wid] + v - 1;
        lrow_s[tid] = (short)lr;
        if (f) utp[lr] = (short)(tps[tid] & 2047);
        __syncthreads();
    }
    int nu = s_nu;

    const float* xb = x + (size_t)n * TPD * ED + ks * KCHUNK;
    const float* wb = g_WeffQ;

    // ---- stage loader: X rows [0,nu), W all 8 s0 tiles ----
    auto load_stage = [&](int st, int b) {
        int kbase = st * KT;
#pragma unroll
        for (int i = 0; i < 4; i++) {
            int gidx = i * 256 + tid;
            int row = gidx >> 2, q = gidx & 3;
            if (row < nu)
                ldgsts16(&Xs[b][row][q * 4],
                         xb + (size_t)utp[row] * ED + kbase + q * 4);
        }
        {
            int s0c = tid >> 5, w32 = tid & 31;  // 256 chunks
            ldgsts16(&Wsm[b][s0c * 132 + w32 * 4],
                     wb + ((size_t)(s0c * 1024) + ks * 128 + st * 4) * 32 + w32 * 4);
        }
        cp_commit();
    };

    load_stage(0, 0);

    int s0m = (int)s0s[tid];
    int lrm = (int)lrow_s[tid];
    bool vm = (e0 + tid) < cnt;

    ull acc[8];
#pragma unroll
    for (int s = 0; s < 8; s++) acc[s] = 0ull;

    for (int st = 0; st < NSTAGE; st++) {
        int b = st & 1;
        if (st + 1 < NSTAGE) {
            load_stage(st + 1, b ^ 1);
            cp_wait<1>();
        } else {
            cp_wait<0>();
        }
        __syncthreads();

        const float* WF = &Wsm[b][0];
#pragma unroll
        for (int q = 0; q < 4; q++) {
            ulonglong2 xv = *(const ulonglong2*)&Xs[b][lrm][q * 4];
            const ull* wq = (const ull*)(WF + s0m * 132 + q * 32);
#pragma unroll
            for (int sp = 0; sp < 4; sp++) {
                ulonglong2 w0 = *(const ulonglong2*)(wq + sp * 2);      // p=0
                ulonglong2 w1 = *(const ulonglong2*)(wq + 8 + sp * 2);  // p=1
                ffma2(acc[2 * sp],     xv.x, w0.x);
                ffma2(acc[2 * sp],     xv.y, w1.x);
                ffma2(acc[2 * sp + 1], xv.x, w0.y);
                ffma2(acc[2 * sp + 1], xv.y, w1.y);
            }
        }
        __syncthreads();
    }

    // store partials (rank = e0 + tid)
    if (vm) {
        float y[8];
#pragma unroll
        for (int s = 0; s < 8; s++) {
            float2 f = *(float2*)&acc[s];
            y[s] = f.x + f.y;
        }
        float* dst = g_part + ((size_t)(ks * NB + n) * RMAX + e0 + tid) * 8;
        *(float4*)(dst)     = make_float4(y[0], y[1], y[2], y[3]);
        *(float4*)(dst + 4) = make_float4(y[4], y[5], y[6], y[7]);
    }
}

// ---------------------------------------------------------------------------
// K4: fused epilogue + default fill. Strip of 256 output rows per block.
// ---------------------------------------------------------------------------
__global__ __launch_bounds__(256) void k4_epi(const float* __restrict__ W3,
                                              const float* __restrict__ b2,
                                              float* __restrict__ out) {
    int n = blockIdx.y;
    int j0 = blockIdx.x * 256;
    int tid = threadIdx.x;
    __shared__ float y2s[256];
    __shared__ float w3s[VD];
    __shared__ float beffs[8];
    if (tid < VD) w3s[tid] = W3[tid];
    if (tid < 8) beffs[tid] = g_beff[tid];
    __syncthreads();

    int count8 = g_count[n] * 8;
    int j = j0 + tid;
    float acc;
    if (j < count8) {
        acc = beffs[j & 7];
#pragma unroll
        for (int ksi = 0; ksi < KS; ksi++)
            acc += g_part[(size_t)(ksi * NB + n) * (RMAX * 8) + j];
    } else {
        acc = b2[0];
    }
    y2s[tid] = acc;
    __syncthreads();

    float* ob = out + ((size_t)n * OUTROWS + j0) * VD;
    const int NF4 = 256 * VD / 4;  // 1088
    for (int f = tid; f < NF4; f += 256) {
        float4 o;
#pragma unroll
        for (int c = 0; c < 4; c++) {
            int idx = f * 4 + c;
            int jj = idx / VD;
            int vv = idx - jj * VD;
            ((float*)&o)[c] = y2s[jj] * w3s[vv];
        }
        *(float4*)(ob + f * 4) = o;
    }
}

// ---------------------------------------------------------------------------
extern "C" void kernel_launch(void* const* d_in, const int* in_sizes, int n_in,
                              void* d_out, int out_size) {
    const float* x     = (const float*)d_in[0];
    const int*   value = (const int*)d_in[1];   // jax x64-off: int32
    const int*   depth = (const int*)d_in[2];
    // d_in[3] = pos, unused
    const float* W1    = (const float*)d_in[4];
    const float* b1    = (const float*)d_in[5];
    const float* W2    = (const float*)d_in[6];
    const float* b2    = (const float*)d_in[7];
    const float* W3    = (const float*)d_in[8];
    float* out = (float*)d_out;

    k01<<<264, 1024>>>(W1, W2, b1, b2, value, depth);
    k3_heavy<<<dim3(512, NB), 256>>>(x);
    k4_epi<<<dim3(OUTROWS / 256, NB), 256>>>(W3, b2, out);
}

// round 10
// speedup vs baseline: 1.4398x; 1.4398x over previous
#include <cuda_runtime.h>
#include <cstdint>

// Problem constants
#define NB   8
#define TPD  2048
#define ED   4096
#define TD   16384
#define VD   17
#define OUTROWS 131072
#define KS   8             // K-splits
#define KCHUNK 512         // ED/KS
#define KT   16            // K per pipeline stage
#define NSTAGE (KCHUNK/KT) // 32
#define MROWS 256          // rows per k3 block
#define NBUF 3             // cp.async ring depth
#define RMAX 16384         // hard upper bound on per-batch masked count
#define XSTRIDE 20

typedef unsigned long long ull;

// k3 dynamic smem layout (floats):
//   Xs   [NBUF][MROWS][XSTRIDE]  = 15360
//   Wsm  [NBUF][4][32]           = 384
//   stp  [MROWS] (int)           = 256
//   sr   [MROWS] (int)           = 256
#define K3_SMEM_BYTES ((NBUF * MROWS * XSTRIDE + NBUF * 128 + 2 * MROWS) * 4)

// Scratch (device globals)
__device__ float g_WeffQ[8 * 1024 * 32];      // [s0][q][32] quad-interleaved Weff
__device__ float g_beff[8];
__device__ int   g_bucket[64 * 2048];         // [(n*8+s0)][slot] = (r<<16)|tp
__device__ int   g_bcount[64];
__device__ int   g_count8[NB];                // 8 * per-batch masked count
__device__ float g_part[(size_t)KS * NB * RMAX * 8];  // [ks][n][r][s]

// ---------------------------------------------------------------------------
__device__ __forceinline__ void ffma2(ull& d, ull a, ull b) {
    asm("fma.rn.f32x2 %0, %1, %2, %0;" : "+l"(d) : "l"(a), "l"(b));
}
__device__ __forceinline__ void ldgsts16(void* dst, const void* src) {
    unsigned saddr = (unsigned)__cvta_generic_to_shared(dst);
    asm volatile("cp.async.cg.shared.global [%0], [%1], 16;\n" :: "r"(saddr), "l"(src));
}
__device__ __forceinline__ void cp_commit() {
    asm volatile("cp.async.commit_group;\n" ::: "memory");
}
template <int N>
__device__ __forceinline__ void cp_wait() {
    asm volatile("cp.async.wait_group %0;\n" :: "n"(N) : "memory");
}

// ---------------------------------------------------------------------------
// K01 fused, 1024 threads/block (R8-proven):
//   blocks [0,8): per-batch argmax + bucketed compaction (coalesced int4,
//                 4 passes of 4096 elems, carried scan bases)
//   blocks [8,264): WeffQ for 16 e-values each (+beff at block 8)
// ---------------------------------------------------------------------------
__global__ __launch_bounds__(1024) void k01(const float* __restrict__ W1,
                                            const float* __restrict__ W2,
                                            const float* __restrict__ b1,
                                            const float* __restrict__ b2,
                                            const int* __restrict__ value,
                                            const int* __restrict__ depth) {
    int bid = blockIdx.x;
    int tid = threadIdx.x;

    if (bid >= 8) {
        // ---- Weff: 16 e-values per block ----
        __shared__ __align__(16) float w2s[512];
        __shared__ __align__(16) float w1r[16][512];
        int e0 = (bid - 8) * 16;
        if (tid < 128) ((float4*)w2s)[tid] = ((const float4*)W2)[tid];
        ((float4*)&w1r[0][0])[tid]        = ((const float4*)(W1 + (size_t)e0 * 512))[tid];
        ((float4*)&w1r[0][0])[tid + 1024] = ((const float4*)(W1 + (size_t)e0 * 512))[tid + 1024];
        __syncthreads();
        int sub = tid >> 6;       // which e (0..15)
        int t64 = tid & 63;
        int s0 = t64 >> 3, s = t64 & 7;
        int e = e0 + sub;
        float acc = 0.f;
#pragma unroll
        for (int c = 0; c < 64; c++) acc += w1r[sub][c * 8 + s0] * w2s[c * 8 + s];
        int q = e >> 2, p = (e >> 1) & 1, h = e & 1;
        g_WeffQ[(s0 * 1024 + q) * 32 + p * 16 + s * 2 + h] = acc;
        if (bid == 8 && tid < 8) {
            float a = 0.f;
#pragma unroll
            for (int c = 0; c < 64; c++) a += b1[c] * w2s[c * 8 + tid];
            g_beff[tid] = a + b2[0];
        }
    } else {
        // ---- prep: batch n, 1024 threads, coalesced int4, 4 passes ----
        int n = bid;
        const int* dep = depth + n * TD;
        const int* val = value + n * TD;
        __shared__ int s_idx;
        __shared__ int wsum[32];
        __shared__ ull wtA[32], wtB[32];
        __shared__ int wbase[32 * 8];
        __shared__ int sb_r;
        __shared__ int sb_s0[8];
        __shared__ int pass_tot;
        __shared__ int pass_tot_s0[8];

        int lane = tid & 31, wid = tid >> 5;  // 32 warps

        int maxv = dep[TD - 1];
        if (tid == 0) { s_idx = TD; sb_r = 0; }
        if (tid < 8) sb_s0[tid] = 0;
        __syncthreads();
        // argmax: first index where dep hits max (dep sorted ascending)
        for (int t0 = tid * 4; t0 < TD; t0 += 4096) {
            int4 d = *(const int4*)(dep + t0);
            int prev = (t0 == 0) ? (maxv - 1) : dep[t0 - 1];
            if (d.x == maxv && prev < maxv) atomicMin(&s_idx, t0);
            if (d.y == maxv && d.x < maxv) atomicMin(&s_idx, t0 + 1);
            if (d.z == maxv && d.y < maxv) atomicMin(&s_idx, t0 + 2);
            if (d.w == maxv && d.z < maxv) atomicMin(&s_idx, t0 + 3);
        }
        __syncthreads();
        int idx = s_idx;
        int bb = n * 8;

        for (int pass = 0; pass < 4; pass++) {
            int t0 = pass * 4096 + tid * 4;
            int4 vv = *(const int4*)(val + t0);
            int vj[4] = {vv.x, vv.y, vv.z, vv.w};
            unsigned mb = 0;
            int cnt = 0;
            ull cA = 0, cB = 0;  // per-s0 counts, 16-bit fields (s0 0-3 / 4-7)
#pragma unroll
            for (int j = 0; j < 4; j++) {
                int t = t0 + j;
                bool m = (t < idx) && (vj[j] == 2);
                mb |= ((unsigned)m) << j;
                cnt += (int)m;
                if (m) {
                    int f = t & 7;
                    if (f < 4) cA += 1ull << (f * 16);
                    else       cB += 1ull << ((f - 4) * 16);
                }
            }
            // warp inclusive scans
            int v = cnt;
            ull ciA = cA, ciB = cB;
#pragma unroll
            for (int o = 1; o < 32; o <<= 1) {
                int u  = __shfl_up_sync(0xffffffffu, v, o);
                ull uA = __shfl_up_sync(0xffffffffu, ciA, o);
                ull uB = __shfl_up_sync(0xffffffffu, ciB, o);
                if (lane >= o) { v += u; ciA += uA; ciB += uB; }
            }
            if (lane == 31) { wsum[wid] = v; wtA[wid] = ciA; wtB[wid] = ciB; }
            __syncthreads();
            if (wid == 0) {
                // exclusive scan of 32 warp totals (rank)
                int w = wsum[lane];
                int wi = w;
#pragma unroll
                for (int o = 1; o < 32; o <<= 1) {
                    int u = __shfl_up_sync(0xffffffffu, wi, o);
                    if (lane >= o) wi += u;
                }
                wsum[lane] = wi - w;
                if (lane == 31) pass_tot = wi;
            } else if (wid == 1 && lane < 8) {
                int s0 = lane;
                int run = 0;
#pragma unroll
                for (int w = 0; w < 32; w++) {
                    int c = (s0 < 4) ? (int)((wtA[w] >> (s0 * 16)) & 0xFFFF)
                                     : (int)((wtB[w] >> ((s0 - 4) * 16)) & 0xFFFF);
                    wbase[w * 8 + s0] = run;
                    run += c;
                }
                pass_tot_s0[s0] = run;
            }
            __syncthreads();
            int r = sb_r + wsum[wid] + (v - cnt);
            ull exA = ciA - cA, exB = ciB - cB;
#pragma unroll
            for (int j = 0; j < 4; j++) {
                if ((mb >> j) & 1u) {
                    int t = t0 + j;
                    int s0 = t & 7;
                    int ex = (s0 < 4) ? (int)((exA >> (s0 * 16)) & 0xFFFF)
                                      : (int)((exB >> ((s0 - 4) * 16)) & 0xFFFF);
                    int slot = sb_s0[s0] + wbase[wid * 8 + s0] + ex;
                    g_bucket[(bb + s0) * 2048 + slot] = (r << 16) | (t >> 3);
                    if (s0 < 4) exA += 1ull << (s0 * 16);
                    else        exB += 1ull << ((s0 - 4) * 16);
                    r++;
                }
            }
            __syncthreads();
            if (tid == 0) sb_r += pass_tot;
            if (tid < 8) sb_s0[tid] += pass_tot_s0[tid];
            __syncthreads();
        }
        if (tid < 8) g_bcount[bb + tid] = sb_s0[tid];
        if (tid == 0) g_count8[n] = 8 * sb_r;
    }
}

// ---------------------------------------------------------------------------
// K3: R8 compute core + 3-buffer cp.async ring (lookahead 2 stages to cover
// DRAM latency). 128 threads/block, 256 rows/block, thread owns 2 rows
// (tid, tid+128) x all 8 s; W reads warp-uniform (broadcast). f32x2 FMA.
// blockIdx.x = rb*64 + ks*8 + s0 (s0,ks fastest for L2 reuse across buckets).
// ---------------------------------------------------------------------------
__global__ __launch_bounds__(128) void k3_heavy(const float* __restrict__ x) {
    int bx = blockIdx.x;
    int s0 = bx & 7, ks = (bx >> 3) & 7, rb = bx >> 6;
    int n = blockIdx.y;
    int bucket = n * 8 + s0;
    int bcnt = g_bcount[bucket];
    int row0 = rb * MROWS;
    if (row0 >= bcnt) return;
    int tid = threadIdx.x;

    extern __shared__ __align__(16) float dsm[];
    float (*Xs)[MROWS][XSTRIDE] = (float(*)[MROWS][XSTRIDE])dsm;       // [NBUF]
    float (*Wsm)[4][32] = (float(*)[4][32])(dsm + NBUF * MROWS * XSTRIDE);
    int* stp_s = (int*)(dsm + NBUF * MROWS * XSTRIDE + NBUF * 128);
    int* sr_s  = stp_s + MROWS;

    // prologue: row metadata (coalesced)
#pragma unroll
    for (int i = 0; i < 2; i++) {
        int li = tid + 128 * i;
        int gr = row0 + li;
        if (gr < bcnt) {
            int p = g_bucket[bucket * 2048 + gr];
            sr_s[li] = p >> 16;
            stp_s[li] = p & 0xFFFF;
        } else {
            sr_s[li] = -1;
            stp_s[li] = 0;
        }
    }
    __syncthreads();

    const float* xb = x + (size_t)n * TPD * ED + ks * KCHUNK;
    const float* wb = g_WeffQ + (size_t)(s0 * 1024 + ks * 128) * 32;

    // loader mapping: gidx = i*128+tid; row = gidx>>2, q = gidx&3
    // (4 lanes cover one row's 4 quads -> 64B contiguous global)
    auto load_stage = [&](int st, int b) {
        int kbase = st * KT;
#pragma unroll
        for (int i = 0; i < 8; i++) {
            int gidx = i * 128 + tid;
            int row = gidx >> 2, q = gidx & 3;
            ldgsts16(&Xs[b][row][q * 4],
                     xb + (size_t)stp_s[row] * ED + kbase + q * 4);
        }
        if (tid < 32) {
            ldgsts16(&Wsm[b][0][tid * 4], wb + st * 128 + tid * 4);
        }
        cp_commit();
    };

    load_stage(0, 0);
    load_stage(1, 1);

    ull acc[2][8];
#pragma unroll
    for (int i = 0; i < 2; i++)
#pragma unroll
        for (int s = 0; s < 8; s++) acc[i][s] = 0ull;

    int buf = 0;
    for (int st = 0; st < NSTAGE; st++) {
        if (st + 2 < NSTAGE) {
            int nb = buf + 2; if (nb >= NBUF) nb -= NBUF;
            load_stage(st + 2, nb);
        }
        // stage st must be complete: allowed pending = issued - (st+1)
        if (st <= NSTAGE - 3)      cp_wait<2>();
        else if (st == NSTAGE - 2) cp_wait<1>();
        else                       cp_wait<0>();
        __syncthreads();

#pragma unroll
        for (int q = 0; q < 4; q++) {
            ulonglong2 xq[2];
#pragma unroll
            for (int i = 0; i < 2; i++)
                xq[i] = *(const ulonglong2*)&Xs[buf][tid + 128 * i][q * 4];
            const ull* wq = (const ull*)&Wsm[buf][q][0];
#pragma unroll
            for (int sp = 0; sp < 4; sp++) {
                ulonglong2 w0 = *(const ulonglong2*)(wq + sp * 2);      // p=0
                ulonglong2 w1 = *(const ulonglong2*)(wq + 8 + sp * 2);  // p=1
#pragma unroll
                for (int i = 0; i < 2; i++) {
                    ffma2(acc[i][2 * sp],     xq[i].x, w0.x);
                    ffma2(acc[i][2 * sp],     xq[i].y, w1.x);
                    ffma2(acc[i][2 * sp + 1], xq[i].x, w0.y);
                    ffma2(acc[i][2 * sp + 1], xq[i].y, w1.y);
                }
            }
        }
        __syncthreads();
        buf++; if (buf >= NBUF) buf = 0;
    }

    // store partials
#pragma unroll
    for (int i = 0; i < 2; i++) {
        int li = tid + 128 * i;
        int rr = sr_s[li];
        if (rr < 0) continue;
        float y[8];
#pragma unroll
        for (int s = 0; s < 8; s++) {
            float2 f = *(float2*)&acc[i][s];
            y[s] = f.x + f.y;
        }
        float* dst = g_part + ((size_t)(ks * NB + n) * RMAX + rr) * 8;
        *(float4*)(dst)     = make_float4(y[0], y[1], y[2], y[3]);
        *(float4*)(dst + 4) = make_float4(y[4], y[5], y[6], y[7]);
    }
}

// ---------------------------------------------------------------------------
// K4: fused epilogue + default fill. Strip of 256 output rows per block.
// ---------------------------------------------------------------------------
__global__ __launch_bounds__(256) void k4_epi(const float* __restrict__ W3,
                                              const float* __restrict__ b2,
                                              float* __restrict__ out) {
    int n = blockIdx.y;
    int j0 = blockIdx.x * 256;
    int tid = threadIdx.x;
    __shared__ float y2s[256];
    __shared__ float w3s[VD];
    __shared__ float beffs[8];
    if (tid < VD) w3s[tid] = W3[tid];
    if (tid < 8) beffs[tid] = g_beff[tid];
    __syncthreads();

    int count8 = g_count8[n];
    int j = j0 + tid;
    float acc;
    if (j < count8) {
        acc = beffs[j & 7];
#pragma unroll
        for (int ksi = 0; ksi < KS; ksi++)
            acc += g_part[(size_t)(ksi * NB + n) * (RMAX * 8) + j];
    } else {
        acc = b2[0];
    }
    y2s[tid] = acc;
    __syncthreads();

    float* ob = out + ((size_t)n * OUTROWS + j0) * VD;
    const int NF4 = 256 * VD / 4;  // 1088
    for (int f = tid; f < NF4; f += 256) {
        float4 o;
#pragma unroll
        for (int c = 0; c < 4; c++) {
            int idx = f * 4 + c;
            int jj = idx / VD;
            int vv = idx - jj * VD;
            ((float*)&o)[c] = y2s[jj] * w3s[vv];
        }
        *(float4*)(ob + f * 4) = o;
    }
}

// ---------------------------------------------------------------------------
extern "C" void kernel_launch(void* const* d_in, const int* in_sizes, int n_in,
                              void* d_out, int out_size) {
    const float* x     = (const float*)d_in[0];
    const int*   value = (const int*)d_in[1];   // jax x64-off: int32
    const int*   depth = (const int*)d_in[2];
    // d_in[3] = pos, unused
    const float* W1    = (const float*)d_in[4];
    const float* b1    = (const float*)d_in[5];
    const float* W2    = (const float*)d_in[6];
    const float* b2    = (const float*)d_in[7];
    const float* W3    = (const float*)d_in[8];
    float* out = (float*)d_out;

    // idempotent; required for >48KB dynamic smem
    cudaFuncSetAttribute(k3_heavy, cudaFuncAttributeMaxDynamicSharedMemorySize,
                         K3_SMEM_BYTES);

    k01<<<264, 1024>>>(W1, W2, b1, b2, value, depth);
    k3_heavy<<<dim3(512, NB), 128, K3_SMEM_BYTES>>>(x);
    k4_epi<<<dim3(OUTROWS / 256, NB), 256>>>(W3, b2, out);
}

// round 12
// speedup vs baseline: 1.8104x; 1.2574x over previous
#include <cuda_runtime.h>
#include <cstdint>

// Problem constants
#define NB   8
#define TPD  2048
#define ED   4096
#define TD   16384
#define VD   17
#define OUTROWS 131072
#define KSP  2              // K splits for the GEMM
#define KC   (ED / KSP)     // 2048 K per block
#define KT   32             // K floats per pipeline stage (128B rows)
#define NSTG (KC / KT)      // 64 stages
#define RMAX 16384

typedef unsigned long long ull;

// Scratch (device globals)
__device__ float g_WeffJ[64 * ED];            // [j=s0*8+s][e], tf32-rounded
__device__ float g_beff[8];
__device__ unsigned short g_entry[NB * RMAX]; // per-batch sorted masked t (rank = index)
__device__ int   g_count8[NB];                // 8 * per-batch masked count
__device__ float g_C[(size_t)KSP * NB * TPD * 64];  // dense GEMM partials (8MB)

// ---------------------------------------------------------------------------
// helpers
// ---------------------------------------------------------------------------
__device__ __forceinline__ void ldgsts16(void* dst, const void* src) {
    unsigned saddr = (unsigned)__cvta_generic_to_shared(dst);
    asm volatile("cp.async.cg.shared.global [%0], [%1], 16;\n" :: "r"(saddr), "l"(src));
}
__device__ __forceinline__ void cp_commit() {
    asm volatile("cp.async.commit_group;\n" ::: "memory");
}
template <int N>
__device__ __forceinline__ void cp_wait() {
    asm volatile("cp.async.wait_group %0;\n" :: "n"(N) : "memory");
}
__device__ __forceinline__ float to_tf32_rna(float f) {
    unsigned u;
    asm("cvt.rna.tf32.f32 %0, %1;" : "=r"(u) : "f"(f));
    return __uint_as_float(u);
}
// XOR-swizzled smem float index: 32-float (128B) rows, 16B chunk swizzle
__device__ __forceinline__ int aidx(int r, int ce) {
    return r * 32 + ((((ce >> 2) ^ (r & 7)) << 2) | (ce & 3));
}
__device__ __forceinline__ void mma_tf32(float* c, const unsigned* a,
                                         unsigned b0, unsigned b1) {
    asm volatile(
        "mma.sync.aligned.m16n8k8.row.col.f32.tf32.tf32.f32 "
        "{%0,%1,%2,%3}, {%4,%5,%6,%7}, {%8,%9}, {%0,%1,%2,%3};"
        : "+f"(c[0]), "+f"(c[1]), "+f"(c[2]), "+f"(c[3])
        : "r"(a[0]), "r"(a[1]), "r"(a[2]), "r"(a[3]), "r"(b0), "r"(b1));
}

// ---------------------------------------------------------------------------
// K01 fused, 1024 threads/block:
//   blocks [0,8): per-batch argmax + masked compaction (sorted t list)
//   blocks [8,264): WeffJ rows for 16 e-values each (+beff at block 8)
// ---------------------------------------------------------------------------
__global__ __launch_bounds__(1024) void k01(const float* __restrict__ W1,
                                            const float* __restrict__ W2,
                                            const float* __restrict__ b1,
                                            const float* __restrict__ b2,
                                            const int* __restrict__ value,
                                            const int* __restrict__ depth) {
    int bid = blockIdx.x;
    int tid = threadIdx.x;

    if (bid >= 8) {
        // ---- WeffJ: 16 e-values per block ----
        __shared__ __align__(16) float w2s[512];
        __shared__ __align__(16) float w1r[16][512];
        int e0 = (bid - 8) * 16;
        if (tid < 128) ((float4*)w2s)[tid] = ((const float4*)W2)[tid];
        ((float4*)&w1r[0][0])[tid]        = ((const float4*)(W1 + (size_t)e0 * 512))[tid];
        ((float4*)&w1r[0][0])[tid + 1024] = ((const float4*)(W1 + (size_t)e0 * 512))[tid + 1024];
        __syncthreads();
        int sub = tid >> 6;       // which e (0..15)
        int t64 = tid & 63;
        int s0 = t64 >> 3, s = t64 & 7;
        int e = e0 + sub;
        float acc = 0.f;
#pragma unroll
        for (int c = 0; c < 64; c++) acc += w1r[sub][c * 8 + s0] * w2s[c * 8 + s];
        g_WeffJ[(size_t)(s0 * 8 + s) * ED + e] = to_tf32_rna(acc);
        if (bid == 8 && tid < 8) {
            float a = 0.f;
#pragma unroll
            for (int c = 0; c < 64; c++) a += b1[c] * w2s[c * 8 + tid];
            g_beff[tid] = a + b2[0];
        }
    } else {
        // ---- prep: batch n, coalesced int4, 4 passes, single rank scan ----
        int n = bid;
        const int* dep = depth + n * TD;
        const int* val = value + n * TD;
        __shared__ int s_idx;
        __shared__ int wsum[32];
        __shared__ int sb_r;
        __shared__ int pass_tot;

        int lane = tid & 31, wid = tid >> 5;  // 32 warps

        int maxv = dep[TD - 1];
        if (tid == 0) { s_idx = TD; sb_r = 0; }
        __syncthreads();
        for (int t0 = tid * 4; t0 < TD; t0 += 4096) {
            int4 d = *(const int4*)(dep + t0);
            int prev = (t0 == 0) ? (maxv - 1) : dep[t0 - 1];
            if (d.x == maxv && prev < maxv) atomicMin(&s_idx, t0);
            if (d.y == maxv && d.x < maxv) atomicMin(&s_idx, t0 + 1);
            if (d.z == maxv && d.y < maxv) atomicMin(&s_idx, t0 + 2);
            if (d.w == maxv && d.z < maxv) atomicMin(&s_idx, t0 + 3);
        }
        __syncthreads();
        int idx = s_idx;

        for (int pass = 0; pass < 4; pass++) {
            int t0 = pass * 4096 + tid * 4;
            int4 vv = *(const int4*)(val + t0);
            int vj[4] = {vv.x, vv.y, vv.z, vv.w};
            unsigned mb = 0;
            int cnt = 0;
#pragma unroll
            for (int j = 0; j < 4; j++) {
                int t = t0 + j;
                bool m = (t < idx) && (vj[j] == 2);
                mb |= ((unsigned)m) << j;
                cnt += (int)m;
            }
            int v = cnt;
#pragma unroll
            for (int o = 1; o < 32; o <<= 1) {
                int u = __shfl_up_sync(0xffffffffu, v, o);
                if (lane >= o) v += u;
            }
            if (lane == 31) wsum[wid] = v;
            __syncthreads();
            if (wid == 0) {
                int w = wsum[lane];
                int wi = w;
#pragma unroll
                for (int o = 1; o < 32; o <<= 1) {
                    int u = __shfl_up_sync(0xffffffffu, wi, o);
                    if (lane >= o) wi += u;
                }
                wsum[lane] = wi - w;
                if (lane == 31) pass_tot = wi;
            }
            __syncthreads();
            int r = sb_r + wsum[wid] + (v - cnt);
#pragma unroll
            for (int j = 0; j < 4; j++) {
                if ((mb >> j) & 1u) {
                    g_entry[n * RMAX + r] = (unsigned short)(t0 + j);
                    r++;
                }
            }
            __syncthreads();
            if (tid == 0) sb_r += pass_tot;
            __syncthreads();
        }
        if (tid == 0) g_count8[n] = 8 * sb_r;
    }
}

// ---------------------------------------------------------------------------
// K3_MMA: dense tf32 mma.sync GEMM.
//   Block (mt, ksp, n): C_part[ksp][n][mt*128..+128][0..64)
//     = X[128 rows, KC] · WeffJ[64 rows, KC]^T
//   128 threads = 4 warps; warp w: rows [w*32, w*32+32) (2 m16 A-tiles) x all
//   8 n8 B-tiles; 64 f32 accum regs/thread. KT=32 double-buffered cp.async
//   stages, XOR-swizzled smem (conflict-free STS + fragment LDS).
// ---------------------------------------------------------------------------
__global__ __launch_bounds__(128) void k3_mma(const float* __restrict__ x) {
    int mt = blockIdx.x, ksp = blockIdx.y, n = blockIdx.z;
    int tid = threadIdx.x;
    int w = tid >> 5, lane = tid & 31;
    int gid = lane >> 2, tig = lane & 3;

    __shared__ __align__(16) float As[2][128 * 32];  // 2 x 16KB
    __shared__ __align__(16) float Bs[2][64 * 32];   // 2 x 8KB   (total 48KB)

    const float* xb = x + (((size_t)n * TPD) + mt * 128) * ED + ksp * KC;
    const float* wb = g_WeffJ + ksp * KC;

    auto load_stage = [&](int st, int b) {
        const float* xs = xb + st * KT;
#pragma unroll
        for (int p = 0; p < 8; p++) {
            int g = p * 128 + tid;
            int r = g >> 3, c = g & 7;          // 8 x 16B chunks per 128B row
            ldgsts16(&As[b][r * 32 + ((c ^ (r & 7)) << 2)],
                     xs + (size_t)r * ED + c * 4);
        }
        const float* ws = wb + st * KT;
#pragma unroll
        for (int p = 0; p < 4; p++) {
            int g = p * 128 + tid;
            int r = g >> 3, c = g & 7;
            ldgsts16(&Bs[b][r * 32 + ((c ^ (r & 7)) << 2)],
                     ws + (size_t)r * ED + c * 4);
        }
        cp_commit();
    };

    load_stage(0, 0);

    float acc[2][8][4];
#pragma unroll
    for (int i = 0; i < 2; i++)
#pragma unroll
        for (int nj = 0; nj < 8; nj++)
#pragma unroll
            for (int q = 0; q < 4; q++) acc[i][nj][q] = 0.f;

    for (int st = 0; st < NSTG; st++) {
        int b = st & 1;
        if (st + 1 < NSTG) {
            load_stage(st + 1, b ^ 1);
            cp_wait<1>();
        } else {
            cp_wait<0>();
        }
        __syncthreads();

#pragma unroll
        for (int kk = 0; kk < 4; kk++) {
            int c0 = kk * 8 + tig;
            unsigned a[2][4];
#pragma unroll
            for (int i = 0; i < 2; i++) {
                int rl = w * 32 + i * 16 + gid;
                int rh = rl + 8;
                a[i][0] = __float_as_uint(As[b][aidx(rl, c0)]);
                a[i][1] = __float_as_uint(As[b][aidx(rh, c0)]);
                a[i][2] = __float_as_uint(As[b][aidx(rl, c0 + 4)]);
                a[i][3] = __float_as_uint(As[b][aidx(rh, c0 + 4)]);
            }
#pragma unroll
            for (int nj = 0; nj < 8; nj++) {
                int j = nj * 8 + gid;
                unsigned b0 = __float_as_uint(Bs[b][aidx(j, c0)]);
                unsigned b1 = __float_as_uint(Bs[b][aidx(j, c0 + 4)]);
                mma_tf32(acc[0][nj], a[0], b0, b1);
                mma_tf32(acc[1][nj], a[1], b0, b1);
            }
        }
        __syncthreads();
    }

    // epilogue: scatter C to g_C[ksp][n][tp][64]
    float* cb = g_C + (((size_t)ksp * NB + n) * TPD + (size_t)mt * 128) * 64;
#pragma unroll
    for (int i = 0; i < 2; i++) {
        int rl = w * 32 + i * 16 + gid;
#pragma unroll
        for (int nj = 0; nj < 8; nj++) {
            int col = nj * 8 + 2 * tig;
            *(float2*)(cb + (size_t)rl * 64 + col) =
                make_float2(acc[i][nj][0], acc[i][nj][1]);
            *(float2*)(cb + (size_t)(rl + 8) * 64 + col) =
                make_float2(acc[i][nj][2], acc[i][nj][3]);
        }
    }
}

// ---------------------------------------------------------------------------
// K4: gather epilogue + default fill. Strip of 256 output rows per block.
// Heavy rows (j < count8): y2 = C[ksp0]+C[ksp1] at (tp, s0*8+s) + beff[s].
// ---------------------------------------------------------------------------
__global__ __launch_bounds__(256) void k4_epi(const float* __restrict__ W3,
                                              const float* __restrict__ b2,
                                              float* __restrict__ out) {
    int n = blockIdx.y;
    int j0 = blockIdx.x * 256;
    int tid = threadIdx.x;
    __shared__ float y2s[256];
    __shared__ float w3s[VD];
    __shared__ float beffs[8];
    if (tid < VD) w3s[tid] = W3[tid];
    if (tid < 8) beffs[tid] = g_beff[tid];
    __syncthreads();

    int count8 = g_count8[n];
    int j = j0 + tid;
    float acc;
    if (j < count8) {
        int r = j >> 3, s = j & 7;
        int t = (int)g_entry[n * RMAX + r];
        int tp = t >> 3, s0 = t & 7;
        size_t ci = ((size_t)n * TPD + tp) * 64 + s0 * 8 + s;
        acc = g_C[ci] + g_C[(size_t)NB * TPD * 64 + ci] + beffs[s];
    } else {
        acc = b2[0];
    }
    y2s[tid] = acc;
    __syncthreads();

    float* ob = out + ((size_t)n * OUTROWS + j0) * VD;
    const int NF4 = 256 * VD / 4;  // 1088
    for (int f = tid; f < NF4; f += 256) {
        float4 o;
#pragma unroll
        for (int c = 0; c < 4; c++) {
            int idx = f * 4 + c;
            int jj = idx / VD;
            int vv = idx - jj * VD;
            ((float*)&o)[c] = y2s[jj] * w3s[vv];
        }
        *(float4*)(ob + f * 4) = o;
    }
}

// ---------------------------------------------------------------------------
extern "C" void kernel_launch(void* const* d_in, const int* in_sizes, int n_in,
                              void* d_out, int out_size) {
    const float* x     = (const float*)d_in[0];
    const int*   value = (const int*)d_in[1];   // jax x64-off: int32
    const int*   depth = (const int*)d_in[2];
    // d_in[3] = pos, unused
    const float* W1    = (const float*)d_in[4];
    const float* b1    = (const float*)d_in[5];
    const float* W2    = (const float*)d_in[6];
    const float* b2    = (const float*)d_in[7];
    const float* W3    = (const float*)d_in[8];
    float* out = (float*)d_out;

    k01<<<264, 1024>>>(W1, W2, b1, b2, value, depth);
    k3_mma<<<dim3(TPD / 128, KSP, NB), 128>>>(x);
    k4_epi<<<dim3(OUTROWS / 256, NB), 256>>>(W3, b2, out);
}

// round 13
// speedup vs baseline: 1.9687x; 1.0874x over previous
#include <cuda_runtime.h>
#include <cstdint>

// Problem constants
#define NB   8
#define TPD  2048
#define ED   4096
#define TD   16384
#define VD   17
#define OUTROWS 131072
#define KSP  4              // K splits for the GEMM
#define KC   (ED / KSP)     // 1024 K per block
#define KT   32             // K floats per pipeline stage (128B rows)
#define NSTG (KC / KT)      // 32 stages
#define MTIL 256            // M rows per block
#define RMAX 16384

typedef unsigned long long ull;

// Scratch (device globals)
__device__ float g_WeffJ[64 * ED];            // [j=s0*8+s][e], tf32-rounded
__device__ float g_beff[8];
__device__ unsigned short g_entry[NB * RMAX]; // per-batch sorted masked t (rank = index)
__device__ int   g_count8[NB];                // 8 * per-batch masked count
__device__ float g_C[(size_t)KSP * NB * TPD * 64];  // dense GEMM partials (16MB)

// ---------------------------------------------------------------------------
// helpers
// ---------------------------------------------------------------------------
__device__ __forceinline__ void ldgsts16(void* dst, const void* src) {
    unsigned saddr = (unsigned)__cvta_generic_to_shared(dst);
    asm volatile("cp.async.cg.shared.global [%0], [%1], 16;\n" :: "r"(saddr), "l"(src));
}
__device__ __forceinline__ void cp_commit() {
    asm volatile("cp.async.commit_group;\n" ::: "memory");
}
template <int N>
__device__ __forceinline__ void cp_wait() {
    asm volatile("cp.async.wait_group %0;\n" :: "n"(N) : "memory");
}
__device__ __forceinline__ float to_tf32_rna(float f) {
    unsigned u;
    asm("cvt.rna.tf32.f32 %0, %1;" : "=r"(u) : "f"(f));
    return __uint_as_float(u);
}
// XOR-swizzled smem float index: 32-float (128B) rows, 16B chunk swizzle
__device__ __forceinline__ int aidx(int r, int ce) {
    return r * 32 + ((((ce >> 2) ^ (r & 7)) << 2) | (ce & 3));
}
__device__ __forceinline__ void mma_tf32(float* c, const unsigned* a,
                                         unsigned b0, unsigned b1) {
    asm volatile(
        "mma.sync.aligned.m16n8k8.row.col.f32.tf32.tf32.f32 "
        "{%0,%1,%2,%3}, {%4,%5,%6,%7}, {%8,%9}, {%0,%1,%2,%3};"
        : "+f"(c[0]), "+f"(c[1]), "+f"(c[2]), "+f"(c[3])
        : "r"(a[0]), "r"(a[1]), "r"(a[2]), "r"(a[3]), "r"(b0), "r"(b1));
}

// ---------------------------------------------------------------------------
// K01 fused, 1024 threads/block:
//   blocks [0,8): per-batch argmax + masked compaction (sorted t list)
//   blocks [8,264): WeffJ rows for 16 e-values each (+beff at block 8)
// ---------------------------------------------------------------------------
__global__ __launch_bounds__(1024) void k01(const float* __restrict__ W1,
                                            const float* __restrict__ W2,
                                            const float* __restrict__ b1,
                                            const float* __restrict__ b2,
                                            const int* __restrict__ value,
                                            const int* __restrict__ depth) {
    int bid = blockIdx.x;
    int tid = threadIdx.x;

    if (bid >= 8) {
        // ---- WeffJ: 16 e-values per block ----
        __shared__ __align__(16) float w2s[512];
        __shared__ __align__(16) float w1r[16][512];
        int e0 = (bid - 8) * 16;
        if (tid < 128) ((float4*)w2s)[tid] = ((const float4*)W2)[tid];
        ((float4*)&w1r[0][0])[tid]        = ((const float4*)(W1 + (size_t)e0 * 512))[tid];
        ((float4*)&w1r[0][0])[tid + 1024] = ((const float4*)(W1 + (size_t)e0 * 512))[tid + 1024];
        __syncthreads();
        int sub = tid >> 6;       // which e (0..15)
        int t64 = tid & 63;
        int s0 = t64 >> 3, s = t64 & 7;
        int e = e0 + sub;
        float acc = 0.f;
#pragma unroll
        for (int c = 0; c < 64; c++) acc += w1r[sub][c * 8 + s0] * w2s[c * 8 + s];
        g_WeffJ[(size_t)(s0 * 8 + s) * ED + e] = to_tf32_rna(acc);
        if (bid == 8 && tid < 8) {
            float a = 0.f;
#pragma unroll
            for (int c = 0; c < 64; c++) a += b1[c] * w2s[c * 8 + tid];
            g_beff[tid] = a + b2[0];
        }
    } else {
        // ---- prep: batch n, coalesced int4, 4 passes, single rank scan ----
        int n = bid;
        const int* dep = depth + n * TD;
        const int* val = value + n * TD;
        __shared__ int s_idx;
        __shared__ int wsum[32];
        __shared__ int sb_r;
        __shared__ int pass_tot;

        int lane = tid & 31, wid = tid >> 5;  // 32 warps

        int maxv = dep[TD - 1];
        if (tid == 0) { s_idx = TD; sb_r = 0; }
        __syncthreads();
        for (int t0 = tid * 4; t0 < TD; t0 += 4096) {
            int4 d = *(const int4*)(dep + t0);
            int prev = (t0 == 0) ? (maxv - 1) : dep[t0 - 1];
            if (d.x == maxv && prev < maxv) atomicMin(&s_idx, t0);
            if (d.y == maxv && d.x < maxv) atomicMin(&s_idx, t0 + 1);
            if (d.z == maxv && d.y < maxv) atomicMin(&s_idx, t0 + 2);
            if (d.w == maxv && d.z < maxv) atomicMin(&s_idx, t0 + 3);
        }
        __syncthreads();
        int idx = s_idx;

        for (int pass = 0; pass < 4; pass++) {
            int t0 = pass * 4096 + tid * 4;
            int4 vv = *(const int4*)(val + t0);
            int vj[4] = {vv.x, vv.y, vv.z, vv.w};
            unsigned mb = 0;
            int cnt = 0;
#pragma unroll
            for (int j = 0; j < 4; j++) {
                int t = t0 + j;
                bool m = (t < idx) && (vj[j] == 2);
                mb |= ((unsigned)m) << j;
                cnt += (int)m;
            }
            int v = cnt;
#pragma unroll
            for (int o = 1; o < 32; o <<= 1) {
                int u = __shfl_up_sync(0xffffffffu, v, o);
                if (lane >= o) v += u;
            }
            if (lane == 31) wsum[wid] = v;
            __syncthreads();
            if (wid == 0) {
                int w = wsum[lane];
                int wi = w;
#pragma unroll
                for (int o = 1; o < 32; o <<= 1) {
                    int u = __shfl_up_sync(0xffffffffu, wi, o);
                    if (lane >= o) wi += u;
                }
                wsum[lane] = wi - w;
                if (lane == 31) pass_tot = wi;
            }
            __syncthreads();
            int r = sb_r + wsum[wid] + (v - cnt);
#pragma unroll
            for (int j = 0; j < 4; j++) {
                if ((mb >> j) & 1u) {
                    g_entry[n * RMAX + r] = (unsigned short)(t0 + j);
                    r++;
                }
            }
            __syncthreads();
            if (tid == 0) sb_r += pass_tot;
            __syncthreads();
        }
        if (tid == 0) g_count8[n] = 8 * sb_r;
    }
}

// ---------------------------------------------------------------------------
// K3_MMA: dense tf32 mma.sync GEMM, warp tile m64n64.
//   Block (mt, ksp, n): C_part[ksp][n][mt*256..+256][0..64)
//     = X[256 rows, KC] · WeffJ[64 rows, KC]^T
//   128 threads = 4 warps; warp w: rows [w*64, w*64+64) (4 m16 A-tiles) x all
//   8 n8 B-tiles; 128 f32 accum regs/thread. KT=32 double-buffered cp.async
//   stages, XOR-swizzled smem (conflict-free STS + fragment LDS).
// ---------------------------------------------------------------------------
__global__ __launch_bounds__(128) void k3_mma(const float* __restrict__ x) {
    int mt = blockIdx.x, ksp = blockIdx.y, n = blockIdx.z;
    int tid = threadIdx.x;
    int w = tid >> 5, lane = tid & 31;
    int gid = lane >> 2, tig = lane & 3;

    extern __shared__ __align__(16) float dsm[];
    float* As = dsm;                 // [2][256*32] = 65536B
    float* Bs = dsm + 2 * 256 * 32;  // [2][64*32]  = 16384B

    const float* xb = x + (((size_t)n * TPD) + mt * MTIL) * ED + ksp * KC;
    const float* wb = g_WeffJ + ksp * KC;

    auto load_stage = [&](int st, int b) {
        const float* xs = xb + st * KT;
        float* Ab = As + b * 256 * 32;
#pragma unroll
        for (int p = 0; p < 16; p++) {
            int g = p * 128 + tid;
            int r = g >> 3, c = g & 7;          // 8 x 16B chunks per 128B row
            ldgsts16(&Ab[r * 32 + ((c ^ (r & 7)) << 2)],
                     xs + (size_t)r * ED + c * 4);
        }
        const float* ws = wb + st * KT;
        float* Bb = Bs + b * 64 * 32;
#pragma unroll
        for (int p = 0; p < 4; p++) {
            int g = p * 128 + tid;
            int r = g >> 3, c = g & 7;
            ldgsts16(&Bb[r * 32 + ((c ^ (r & 7)) << 2)],
                     ws + (size_t)r * ED + c * 4);
        }
        cp_commit();
    };

    load_stage(0, 0);

    float acc[4][8][4];
#pragma unroll
    for (int i = 0; i < 4; i++)
#pragma unroll
        for (int nj = 0; nj < 8; nj++)
#pragma unroll
            for (int q = 0; q < 4; q++) acc[i][nj][q] = 0.f;

    for (int st = 0; st < NSTG; st++) {
        int b = st & 1;
        if (st + 1 < NSTG) {
            load_stage(st + 1, b ^ 1);
            cp_wait<1>();
        } else {
            cp_wait<0>();
        }
        __syncthreads();

        const float* Ab = As + b * 256 * 32;
        const float* Bb = Bs + b * 64 * 32;
#pragma unroll
        for (int kk = 0; kk < 4; kk++) {
            int c0 = kk * 8 + tig;
            unsigned a[4][4];
#pragma unroll
            for (int i = 0; i < 4; i++) {
                int rl = w * 64 + i * 16 + gid;
                int rh = rl + 8;
                a[i][0] = __float_as_uint(Ab[aidx(rl, c0)]);
                a[i][1] = __float_as_uint(Ab[aidx(rh, c0)]);
                a[i][2] = __float_as_uint(Ab[aidx(rl, c0 + 4)]);
                a[i][3] = __float_as_uint(Ab[aidx(rh, c0 + 4)]);
            }
#pragma unroll
            for (int nj = 0; nj < 8; nj++) {
                int j = nj * 8 + gid;
                unsigned b0 = __float_as_uint(Bb[aidx(j, c0)]);
                unsigned b1 = __float_as_uint(Bb[aidx(j, c0 + 4)]);
#pragma unroll
                for (int i = 0; i < 4; i++)
                    mma_tf32(acc[i][nj], a[i], b0, b1);
            }
        }
        __syncthreads();
    }

    // epilogue: scatter C to g_C[ksp][n][tp][64]
    float* cb = g_C + (((size_t)ksp * NB + n) * TPD + (size_t)mt * MTIL) * 64;
#pragma unroll
    for (int i = 0; i < 4; i++) {
        int rl = w * 64 + i * 16 + gid;
#pragma unroll
        for (int nj = 0; nj < 8; nj++) {
            int col = nj * 8 + 2 * tig;
            *(float2*)(cb + (size_t)rl * 64 + col) =
                make_float2(acc[i][nj][0], acc[i][nj][1]);
            *(float2*)(cb + (size_t)(rl + 8) * 64 + col) =
                make_float2(acc[i][nj][2], acc[i][nj][3]);
        }
    }
}

#define K3_SMEM ((2 * 256 * 32 + 2 * 64 * 32) * 4)  // 81920 B

// ---------------------------------------------------------------------------
// K4: gather epilogue + default fill. Strip of 256 output rows per block.
// Heavy rows (j < count8): y2 = sum_ksp C at (tp, s0*8+s) + beff[s].
// ---------------------------------------------------------------------------
__global__ __launch_bounds__(256) void k4_epi(const float* __restrict__ W3,
                                              const float* __restrict__ b2,
                                              float* __restrict__ out) {
    int n = blockIdx.y;
    int j0 = blockIdx.x * 256;
    int tid = threadIdx.x;
    __shared__ float y2s[256];
    __shared__ float w3s[VD];
    __shared__ float beffs[8];
    if (tid < VD) w3s[tid] = W3[tid];
    if (tid < 8) beffs[tid] = g_beff[tid];
    __syncthreads();

    int count8 = g_count8[n];
    int j = j0 + tid;
    float acc;
    if (j < count8) {
        int r = j >> 3, s = j & 7;
        int t = (int)g_entry[n * RMAX + r];
        int tp = t >> 3, s0 = t & 7;
        size_t ci = ((size_t)n * TPD + tp) * 64 + s0 * 8 + s;
        acc = beffs[s];
#pragma unroll
        for (int kq = 0; kq < KSP; kq++)
            acc += g_C[(size_t)kq * NB * TPD * 64 + ci];
    } else {
        acc = b2[0];
    }
    y2s[tid] = acc;
    __syncthreads();

    float* ob = out + ((size_t)n * OUTROWS + j0) * VD;
    const int NF4 = 256 * VD / 4;  // 1088
    for (int f = tid; f < NF4; f += 256) {
        float4 o;
#pragma unroll
        for (int c = 0; c < 4; c++) {
            int idx = f * 4 + c;
            int jj = idx / VD;
            int vv = idx - jj * VD;
            ((float*)&o)[c] = y2s[jj] * w3s[vv];
        }
        *(float4*)(ob + f * 4) = o;
    }
}

// ---------------------------------------------------------------------------
extern "C" void kernel_launch(void* const* d_in, const int* in_sizes, int n_in,
                              void* d_out, int out_size) {
    const float* x     = (const float*)d_in[0];
    const int*   value = (const int*)d_in[1];   // jax x64-off: int32
    const int*   depth = (const int*)d_in[2];
    // d_in[3] = pos, unused
    const float* W1    = (const float*)d_in[4];
    const float* b1    = (const float*)d_in[5];
    const float* W2    = (const float*)d_in[6];
    const float* b2    = (const float*)d_in[7];
    const float* W3    = (const float*)d_in[8];
    float* out = (float*)d_out;

    cudaFuncSetAttribute(k3_mma, cudaFuncAttributeMaxDynamicSharedMemorySize,
                         K3_SMEM);

    k01<<<264, 1024>>>(W1, W2, b1, b2, value, depth);
    k3_mma<<<dim3(TPD / MTIL, KSP, NB), 128, K3_SMEM>>>(x);
    k4_epi<<<dim3(OUTROWS / 256, NB), 256>>>(W3, b2, out);
}